// round 13
// baseline (speedup 1.0000x reference)
#include <cuda_runtime.h>
#include <math.h>

#define CHUNKS 4
#define MAXB   1024
#define MAXC   (MAXB * CHUNKS)
#define NTHR   128

// Per-(row,chunk) partials: exp-sums and dot products.
__device__ float g_s[3 * MAXC];   // sum exp(v) per stream
__device__ float g_a[4 * MAXC];   // a0,a1,a2 (dot with x), ax (sum x)
__device__ float g_lat[3 * MAXB]; // per-row k1, k2, bw (written by chunk 0)
__device__ unsigned int g_count;  // arrival counter

__device__ __forceinline__ float exp4(float4 v) {
    return (__expf(v.x) + __expf(v.y)) + (__expf(v.z) + __expf(v.w));
}
__device__ __forceinline__ float dot4(float4 a, float4 b, float acc) {
    return fmaf(a.x, b.x, fmaf(a.y, b.y, fmaf(a.z, b.z, fmaf(a.w, b.w, acc))));
}
__device__ __forceinline__ float sum4(float4 v) {
    return (v.x + v.y) + (v.z + v.w);
}

__global__ __launch_bounds__(NTHR, 6)
void fused_loss_kernel(const float* __restrict__ recon_x,
                       const float* __restrict__ x,
                       const float* __restrict__ lt,
                       const float* __restrict__ lr,
                       const float* __restrict__ mu,
                       const float* __restrict__ lv,
                       const float* __restrict__ pmu,
                       const float* __restrict__ plv,
                       float* __restrict__ out,
                       int B, int N, int D)
{
    const int blk = blockIdx.x;
    const int b   = blk / CHUNKS;           // row
    const int c   = blk % CHUNKS;           // column chunk
    const size_t rowN = (size_t)b * N;
    const size_t rowD = (size_t)b * D;

    const int n4 = N >> 2;
    const int f0 = (int)(((long long)c       * n4) / CHUNKS);
    const int f1 = (int)(((long long)(c + 1) * n4) / CHUNKS);

    const float4* rx4 = (const float4*)(recon_x + rowN);
    const float4* xx4 = (const float4*)(x + rowN);
    const float4* lt4 = (const float4*)(lt + rowN);
    const float4* lr4 = (const float4*)(lr + rowN);

    float s0 = 0.f, s1 = 0.f, s2 = 0.f;
    float a0 = 0.f, a1 = 0.f, a2 = 0.f, ax = 0.f;

    int i = f0 + threadIdx.x;
    // unroll x3: 12 LDG.128 front-batched per warp before ANY consume.
    for (; i + 2 * NTHR < f1; i += 3 * NTHR) {
        // --- issue all 12 loads first (streaming, evict-first) ---
        float4 r_a = __ldcs(rx4 + i);
        float4 r_b = __ldcs(rx4 + i + NTHR);
        float4 r_c = __ldcs(rx4 + i + 2 * NTHR);
        float4 x_a = __ldcs(xx4 + i);
        float4 x_b = __ldcs(xx4 + i + NTHR);
        float4 x_c = __ldcs(xx4 + i + 2 * NTHR);
        float4 t_a = __ldcs(lt4 + i);
        float4 t_b = __ldcs(lt4 + i + NTHR);
        float4 t_c = __ldcs(lt4 + i + 2 * NTHR);
        float4 l_a = __ldcs(lr4 + i);
        float4 l_b = __ldcs(lr4 + i + NTHR);
        float4 l_c = __ldcs(lr4 + i + 2 * NTHR);

        // --- consume ---
        s0 += exp4(r_a) + exp4(r_b) + exp4(r_c);
        s1 += exp4(t_a) + exp4(t_b) + exp4(t_c);
        s2 += exp4(l_a) + exp4(l_b) + exp4(l_c);

        a0 = dot4(r_a, x_a, a0); a0 = dot4(r_b, x_b, a0); a0 = dot4(r_c, x_c, a0);
        a1 = dot4(t_a, x_a, a1); a1 = dot4(t_b, x_b, a1); a1 = dot4(t_c, x_c, a1);
        a2 = dot4(l_a, x_a, a2); a2 = dot4(l_b, x_b, a2); a2 = dot4(l_c, x_c, a2);
        ax += sum4(x_a) + sum4(x_b) + sum4(x_c);
    }
    for (; i < f1; i += NTHR) {
        float4 vr = __ldcs(rx4 + i);
        float4 vx = __ldcs(xx4 + i);
        float4 vt = __ldcs(lt4 + i);
        float4 vl = __ldcs(lr4 + i);
        s0 += exp4(vr);
        s1 += exp4(vt);
        s2 += exp4(vl);
        a0 = dot4(vr, vx, a0);
        a1 = dot4(vt, vx, a1);
        a2 = dot4(vl, vx, a2);
        ax += sum4(vx);
    }
    // scalar tail of the row (N % 4), handled by the last chunk
    if (c == CHUNKS - 1) {
        for (int j = (n4 << 2) + threadIdx.x; j < N; j += NTHR) {
            float v0 = recon_x[rowN + j];
            float vx = x[rowN + j];
            float v1 = lt[rowN + j];
            float v2 = lr[rowN + j];
            s0 += __expf(v0); s1 += __expf(v1); s2 += __expf(v2);
            a0 = fmaf(v0, vx, a0); a1 = fmaf(v1, vx, a1); a2 = fmaf(v2, vx, a2);
            ax += vx;
        }
    }

    // latent row (chunk 0 only): KLDs + diagonal Bures-Wasserstein
    float k1 = 0.f, k2 = 0.f, bw = 0.f;
    if (c == 0) {
        for (int j = threadIdx.x; j < D; j += NTHR) {
            float lvv  = lv[rowD + j];
            float plvv = plv[rowD + j];
            float e1 = __expf(lvv);
            float e2 = __expf(plvv);
            float cc = __expf(0.5f * (lvv + plvv));   // sqrt(e1*e2)
            k1 += 1.0f + lvv  - e1;
            k2 += 1.0f + plvv - e2;
            float dm = mu[rowD + j] - pmu[rowD + j];
            bw = fmaf(dm, dm, bw) + e1 + e2 - 2.0f * cc;
        }
    }

    // ---- block reduction of 10 plain sums (4 warps) ----
    const unsigned FULL = 0xFFFFFFFFu;
    #pragma unroll
    for (int o = 16; o; o >>= 1) {
        s0 += __shfl_xor_sync(FULL, s0, o);
        s1 += __shfl_xor_sync(FULL, s1, o);
        s2 += __shfl_xor_sync(FULL, s2, o);
        a0 += __shfl_xor_sync(FULL, a0, o);
        a1 += __shfl_xor_sync(FULL, a1, o);
        a2 += __shfl_xor_sync(FULL, a2, o);
        ax += __shfl_xor_sync(FULL, ax, o);
        k1 += __shfl_xor_sync(FULL, k1, o);
        k2 += __shfl_xor_sync(FULL, k2, o);
        bw += __shfl_xor_sync(FULL, bw, o);
    }

    __shared__ float sh[4][10];
    const int warp = threadIdx.x >> 5;
    const int lane = threadIdx.x & 31;
    if (lane == 0) {
        sh[warp][0] = s0; sh[warp][1] = s1; sh[warp][2] = s2;
        sh[warp][3] = a0; sh[warp][4] = a1; sh[warp][5] = a2;
        sh[warp][6] = ax; sh[warp][7] = k1; sh[warp][8] = k2; sh[warp][9] = bw;
    }
    __syncthreads();

    if (warp == 0) {
        if (lane < 4) {
            s0 = sh[lane][0]; s1 = sh[lane][1]; s2 = sh[lane][2];
            a0 = sh[lane][3]; a1 = sh[lane][4]; a2 = sh[lane][5];
            ax = sh[lane][6]; k1 = sh[lane][7]; k2 = sh[lane][8]; bw = sh[lane][9];
        } else {
            s0 = s1 = s2 = a0 = a1 = a2 = ax = k1 = k2 = bw = 0.f;
        }
        #pragma unroll
        for (int o = 2; o; o >>= 1) {
            s0 += __shfl_xor_sync(FULL, s0, o);
            s1 += __shfl_xor_sync(FULL, s1, o);
            s2 += __shfl_xor_sync(FULL, s2, o);
            a0 += __shfl_xor_sync(FULL, a0, o);
            a1 += __shfl_xor_sync(FULL, a1, o);
            a2 += __shfl_xor_sync(FULL, a2, o);
            ax += __shfl_xor_sync(FULL, ax, o);
            k1 += __shfl_xor_sync(FULL, k1, o);
            k2 += __shfl_xor_sync(FULL, k2, o);
            bw += __shfl_xor_sync(FULL, bw, o);
        }
        if (lane == 0) {
            g_s[0 * MAXC + blk] = s0;
            g_s[1 * MAXC + blk] = s1;
            g_s[2 * MAXC + blk] = s2;
            g_a[0 * MAXC + blk] = a0;
            g_a[1 * MAXC + blk] = a1;
            g_a[2 * MAXC + blk] = a2;
            g_a[3 * MAXC + blk] = ax;
            if (c == 0) {
                g_lat[0 * MAXB + b] = k1;
                g_lat[1 * MAXB + b] = k2;
                g_lat[2 * MAXB + b] = bw;
            }
        }
    }

    // ---- last-block-done: finalize inline ----
    __shared__ bool isLast;
    __threadfence();
    __syncthreads();
    if (threadIdx.x == 0) {
        unsigned int old = atomicAdd(&g_count, 1u);
        isLast = (old == gridDim.x - 1);
    }
    __syncthreads();
    if (!isLast) return;

    __threadfence();

    float t0 = 0.f, t1 = 0.f, t2 = 0.f, t3 = 0.f, t4v = 0.f, t5 = 0.f;
    for (int r = threadIdx.x; r < B; r += NTHR) {
        float rs0 = 0.f, rs1 = 0.f, rs2 = 0.f;
        float ra0 = 0.f, ra1 = 0.f, ra2 = 0.f, rax = 0.f;
        #pragma unroll
        for (int cc = 0; cc < CHUNKS; cc++) {
            int idx = r * CHUNKS + cc;
            rs0 += g_s[0 * MAXC + idx];
            rs1 += g_s[1 * MAXC + idx];
            rs2 += g_s[2 * MAXC + idx];
            ra0 += g_a[0 * MAXC + idx];
            ra1 += g_a[1 * MAXC + idx];
            ra2 += g_a[2 * MAXC + idx];
            rax += g_a[3 * MAXC + idx];
        }
        t0 += ra0 - logf(rs0) * rax;  // merged
        t1 += ra1 - logf(rs1) * rax;  // text
        t2 += ra2 - logf(rs2) * rax;  // rec
        t3  += g_lat[0 * MAXB + r];
        t4v += g_lat[1 * MAXB + r];
        t5  += g_lat[2 * MAXB + r];
    }

    #pragma unroll
    for (int o = 16; o; o >>= 1) {
        t0  += __shfl_xor_sync(FULL, t0,  o);
        t1  += __shfl_xor_sync(FULL, t1,  o);
        t2  += __shfl_xor_sync(FULL, t2,  o);
        t3  += __shfl_xor_sync(FULL, t3,  o);
        t4v += __shfl_xor_sync(FULL, t4v, o);
        t5  += __shfl_xor_sync(FULL, t5,  o);
    }
    __shared__ float sh2[4][6];
    if (lane == 0) {
        sh2[warp][0] = t0; sh2[warp][1] = t1; sh2[warp][2] = t2;
        sh2[warp][3] = t3; sh2[warp][4] = t4v; sh2[warp][5] = t5;
    }
    __syncthreads();
    if (threadIdx.x == 0) {
        float u[6] = {0.f, 0.f, 0.f, 0.f, 0.f, 0.f};
        for (int w = 0; w < 4; w++) {
            u[0] += sh2[w][0]; u[1] += sh2[w][1]; u[2] += sh2[w][2];
            u[3] += sh2[w][3]; u[4] += sh2[w][4]; u[5] += sh2[w][5];
        }
        float invBN = 1.0f / ((float)B * (float)N);
        float bce_m = -u[0] * invBN;
        float bce_t = -u[1] * invBN;
        float bce_r = -u[2] * invBN;
        float BCE = (bce_m + bce_t + bce_r) * (1.0f / 3.0f);
        float invBD = 1.0f / ((float)B * (float)D);
        float kld1 = -0.5f * u[3] * invBD;
        float kld2 = -0.5f * u[4] * invBD;
        float W = u[5] / (float)B;
        out[0] = BCE + 0.5f * (kld1 + kld2) + W;  // l (anneal=1, epsilon=1)
        out[1] = BCE;
        out[2] = W;
        out[3] = bce_r;
        out[4] = bce_t;
        out[5] = bce_m;
        g_count = 0;  // reset for next graph replay
    }
}

extern "C" void kernel_launch(void* const* d_in, const int* in_sizes, int n_in,
                              void* d_out, int out_size) {
    const float* recon_x = (const float*)d_in[0];
    const float* x       = (const float*)d_in[1];
    const float* mu      = (const float*)d_in[2];
    const float* logvar  = (const float*)d_in[3];
    const float* lt      = (const float*)d_in[4];
    const float* lr      = (const float*)d_in[5];
    const float* pmu     = (const float*)d_in[6];
    const float* plv     = (const float*)d_in[7];

    const int D = 400;
    const int B = in_sizes[2] / D;
    const int N = in_sizes[0] / B;

    fused_loss_kernel<<<B * CHUNKS, NTHR>>>(recon_x, x, lt, lr, mu, logvar,
                                            pmu, plv, (float*)d_out, B, N, D);
}

// round 15
// speedup vs baseline: 1.2711x; 1.2711x over previous
#include <cuda_runtime.h>
#include <math.h>

#define CHUNKS 3
#define MAXB   1024
#define MAXC   (MAXB * CHUNKS)
#define NTHR   256

// Per-(row,chunk) partials: exp-sums and dot products.
__device__ float g_s[3 * MAXC];   // sum exp(v) per stream
__device__ float g_a[4 * MAXC];   // a0,a1,a2 (dot with x), ax (sum x)
__device__ float g_lat[3 * MAXB]; // per-row k1, k2, bw (written by chunk 0)
__device__ unsigned int g_count;  // arrival counter

__device__ __forceinline__ float exp4(float4 v) {
    return (__expf(v.x) + __expf(v.y)) + (__expf(v.z) + __expf(v.w));
}
__device__ __forceinline__ float dot4(float4 a, float4 b, float acc) {
    return fmaf(a.x, b.x, fmaf(a.y, b.y, fmaf(a.z, b.z, fmaf(a.w, b.w, acc))));
}
__device__ __forceinline__ float sum4(float4 v) {
    return (v.x + v.y) + (v.z + v.w);
}

__global__ __launch_bounds__(NTHR)
void fused_loss_kernel(const float* __restrict__ recon_x,
                       const float* __restrict__ x,
                       const float* __restrict__ lt,
                       const float* __restrict__ lr,
                       const float* __restrict__ mu,
                       const float* __restrict__ lv,
                       const float* __restrict__ pmu,
                       const float* __restrict__ plv,
                       float* __restrict__ out,
                       int B, int N, int D)
{
    const int blk = blockIdx.x;
    const int b   = blk / CHUNKS;           // row
    const int c   = blk % CHUNKS;           // column chunk
    const size_t rowN = (size_t)b * N;
    const size_t rowD = (size_t)b * D;

    const int n4 = N >> 2;
    const int f0 = (int)(((long long)c       * n4) / CHUNKS);
    const int f1 = (int)(((long long)(c + 1) * n4) / CHUNKS);

    const float4* rx4 = (const float4*)(recon_x + rowN);
    const float4* xx4 = (const float4*)(x + rowN);
    const float4* lt4 = (const float4*)(lt + rowN);
    const float4* lr4 = (const float4*)(lr + rowN);

    float s0 = 0.f, s1 = 0.f, s2 = 0.f;
    float a0 = 0.f, a1 = 0.f, a2 = 0.f, ax = 0.f;

#define CONSUME(vr, vx, vt, vl)                \
    do {                                       \
        s0 += exp4(vr);                        \
        s1 += exp4(vt);                        \
        s2 += exp4(vl);                        \
        a0 = dot4(vr, vx, a0);                 \
        a1 = dot4(vt, vx, a1);                 \
        a2 = dot4(vl, vx, a2);                 \
        ax += sum4(vx);                        \
    } while (0)

    // ---- 3-deep register-rotation pipeline over the chunk span ----
    int i = f0 + (int)threadIdx.x;
    const int trips = (i < f1) ? ((f1 - 1 - i) / NTHR) + 1 : 0;

    float4 r0v, x0v, t0v, l0v;
    float4 r1v, x1v, t1v, l1v;
    float4 r2v, x2v, t2v, l2v;

    if (trips > 0) { r0v = rx4[i];            x0v = xx4[i];            t0v = lt4[i];            l0v = lr4[i]; }
    if (trips > 1) { int j = i + NTHR;        r1v = rx4[j]; x1v = xx4[j]; t1v = lt4[j]; l1v = lr4[j]; }
    if (trips > 2) { int j = i + 2 * NTHR;    r2v = rx4[j]; x2v = xx4[j]; t2v = lt4[j]; l2v = lr4[j]; }

    for (int k = 3; k < trips; k++) {
        const int j = i + 3 * NTHR;
        float4 nr = rx4[j];
        float4 nx = xx4[j];
        float4 nt = lt4[j];
        float4 nl = lr4[j];
        CONSUME(r0v, x0v, t0v, l0v);
        r0v = r1v; x0v = x1v; t0v = t1v; l0v = l1v;
        r1v = r2v; x1v = x2v; t1v = t2v; l1v = l2v;
        r2v = nr;  x2v = nx;  t2v = nt;  l2v = nl;
        i += NTHR;
    }
    // drain
    if (trips >= 3) {
        CONSUME(r0v, x0v, t0v, l0v);
        r0v = r1v; x0v = x1v; t0v = t1v; l0v = l1v;
        r1v = r2v; x1v = x2v; t1v = t2v; l1v = l2v;
    }
    if (trips >= 2) {
        CONSUME(r0v, x0v, t0v, l0v);
        r0v = r1v; x0v = x1v; t0v = t1v; l0v = l1v;
    }
    if (trips >= 1) {
        CONSUME(r0v, x0v, t0v, l0v);
    }
#undef CONSUME

    // scalar tail of the row (N % 4), handled by the last chunk
    if (c == CHUNKS - 1) {
        for (int j = (n4 << 2) + threadIdx.x; j < N; j += NTHR) {
            float v0 = recon_x[rowN + j];
            float vx = x[rowN + j];
            float v1 = lt[rowN + j];
            float v2 = lr[rowN + j];
            s0 += __expf(v0); s1 += __expf(v1); s2 += __expf(v2);
            a0 = fmaf(v0, vx, a0); a1 = fmaf(v1, vx, a1); a2 = fmaf(v2, vx, a2);
            ax += vx;
        }
    }

    // latent row (chunk 0 only): KLDs + diagonal Bures-Wasserstein
    float k1 = 0.f, k2 = 0.f, bw = 0.f;
    if (c == 0) {
        for (int j = threadIdx.x; j < D; j += NTHR) {
            float lvv  = lv[rowD + j];
            float plvv = plv[rowD + j];
            float e1 = __expf(lvv);
            float e2 = __expf(plvv);
            float cc = __expf(0.5f * (lvv + plvv));   // sqrt(e1*e2)
            k1 += 1.0f + lvv  - e1;
            k2 += 1.0f + plvv - e2;
            float dm = mu[rowD + j] - pmu[rowD + j];
            bw = fmaf(dm, dm, bw) + e1 + e2 - 2.0f * cc;
        }
    }

    // ---- block reduction of 10 plain sums (8 warps) ----
    const unsigned FULL = 0xFFFFFFFFu;
    #pragma unroll
    for (int o = 16; o; o >>= 1) {
        s0 += __shfl_xor_sync(FULL, s0, o);
        s1 += __shfl_xor_sync(FULL, s1, o);
        s2 += __shfl_xor_sync(FULL, s2, o);
        a0 += __shfl_xor_sync(FULL, a0, o);
        a1 += __shfl_xor_sync(FULL, a1, o);
        a2 += __shfl_xor_sync(FULL, a2, o);
        ax += __shfl_xor_sync(FULL, ax, o);
        k1 += __shfl_xor_sync(FULL, k1, o);
        k2 += __shfl_xor_sync(FULL, k2, o);
        bw += __shfl_xor_sync(FULL, bw, o);
    }

    __shared__ float sh[8][10];
    const int warp = threadIdx.x >> 5;
    const int lane = threadIdx.x & 31;
    if (lane == 0) {
        sh[warp][0] = s0; sh[warp][1] = s1; sh[warp][2] = s2;
        sh[warp][3] = a0; sh[warp][4] = a1; sh[warp][5] = a2;
        sh[warp][6] = ax; sh[warp][7] = k1; sh[warp][8] = k2; sh[warp][9] = bw;
    }
    __syncthreads();

    if (warp == 0) {
        if (lane < 8) {
            s0 = sh[lane][0]; s1 = sh[lane][1]; s2 = sh[lane][2];
            a0 = sh[lane][3]; a1 = sh[lane][4]; a2 = sh[lane][5];
            ax = sh[lane][6]; k1 = sh[lane][7]; k2 = sh[lane][8]; bw = sh[lane][9];
        } else {
            s0 = s1 = s2 = a0 = a1 = a2 = ax = k1 = k2 = bw = 0.f;
        }
        #pragma unroll
        for (int o = 4; o; o >>= 1) {
            s0 += __shfl_xor_sync(FULL, s0, o);
            s1 += __shfl_xor_sync(FULL, s1, o);
            s2 += __shfl_xor_sync(FULL, s2, o);
            a0 += __shfl_xor_sync(FULL, a0, o);
            a1 += __shfl_xor_sync(FULL, a1, o);
            a2 += __shfl_xor_sync(FULL, a2, o);
            ax += __shfl_xor_sync(FULL, ax, o);
            k1 += __shfl_xor_sync(FULL, k1, o);
            k2 += __shfl_xor_sync(FULL, k2, o);
            bw += __shfl_xor_sync(FULL, bw, o);
        }
        if (lane == 0) {
            g_s[0 * MAXC + blk] = s0;
            g_s[1 * MAXC + blk] = s1;
            g_s[2 * MAXC + blk] = s2;
            g_a[0 * MAXC + blk] = a0;
            g_a[1 * MAXC + blk] = a1;
            g_a[2 * MAXC + blk] = a2;
            g_a[3 * MAXC + blk] = ax;
            if (c == 0) {
                g_lat[0 * MAXB + b] = k1;
                g_lat[1 * MAXB + b] = k2;
                g_lat[2 * MAXB + b] = bw;
            }
        }
    }

    // ---- last-block-done: finalize inline ----
    __shared__ bool isLast;
    __threadfence();
    __syncthreads();
    if (threadIdx.x == 0) {
        unsigned int old = atomicAdd(&g_count, 1u);
        isLast = (old == gridDim.x - 1);
    }
    __syncthreads();
    if (!isLast) return;

    __threadfence();

    float t0 = 0.f, t1 = 0.f, t2 = 0.f, t3 = 0.f, t4v = 0.f, t5 = 0.f;
    for (int r = threadIdx.x; r < B; r += NTHR) {
        float rs0 = 0.f, rs1 = 0.f, rs2 = 0.f;
        float ra0 = 0.f, ra1 = 0.f, ra2 = 0.f, rax = 0.f;
        #pragma unroll
        for (int cc = 0; cc < CHUNKS; cc++) {
            int idx = r * CHUNKS + cc;
            rs0 += g_s[0 * MAXC + idx];
            rs1 += g_s[1 * MAXC + idx];
            rs2 += g_s[2 * MAXC + idx];
            ra0 += g_a[0 * MAXC + idx];
            ra1 += g_a[1 * MAXC + idx];
            ra2 += g_a[2 * MAXC + idx];
            rax += g_a[3 * MAXC + idx];
        }
        t0 += ra0 - logf(rs0) * rax;  // merged
        t1 += ra1 - logf(rs1) * rax;  // text
        t2 += ra2 - logf(rs2) * rax;  // rec
        t3  += g_lat[0 * MAXB + r];
        t4v += g_lat[1 * MAXB + r];
        t5  += g_lat[2 * MAXB + r];
    }

    #pragma unroll
    for (int o = 16; o; o >>= 1) {
        t0  += __shfl_xor_sync(FULL, t0,  o);
        t1  += __shfl_xor_sync(FULL, t1,  o);
        t2  += __shfl_xor_sync(FULL, t2,  o);
        t3  += __shfl_xor_sync(FULL, t3,  o);
        t4v += __shfl_xor_sync(FULL, t4v, o);
        t5  += __shfl_xor_sync(FULL, t5,  o);
    }
    __shared__ float sh2[8][6];
    if (lane == 0) {
        sh2[warp][0] = t0; sh2[warp][1] = t1; sh2[warp][2] = t2;
        sh2[warp][3] = t3; sh2[warp][4] = t4v; sh2[warp][5] = t5;
    }
    __syncthreads();
    if (threadIdx.x == 0) {
        float u[6] = {0.f, 0.f, 0.f, 0.f, 0.f, 0.f};
        for (int w = 0; w < 8; w++) {
            u[0] += sh2[w][0]; u[1] += sh2[w][1]; u[2] += sh2[w][2];
            u[3] += sh2[w][3]; u[4] += sh2[w][4]; u[5] += sh2[w][5];
        }
        float invBN = 1.0f / ((float)B * (float)N);
        float bce_m = -u[0] * invBN;
        float bce_t = -u[1] * invBN;
        float bce_r = -u[2] * invBN;
        float BCE = (bce_m + bce_t + bce_r) * (1.0f / 3.0f);
        float invBD = 1.0f / ((float)B * (float)D);
        float kld1 = -0.5f * u[3] * invBD;
        float kld2 = -0.5f * u[4] * invBD;
        float W = u[5] / (float)B;
        out[0] = BCE + 0.5f * (kld1 + kld2) + W;  // l (anneal=1, epsilon=1)
        out[1] = BCE;
        out[2] = W;
        out[3] = bce_r;
        out[4] = bce_t;
        out[5] = bce_m;
        g_count = 0;  // reset for next graph replay
    }
}

extern "C" void kernel_launch(void* const* d_in, const int* in_sizes, int n_in,
                              void* d_out, int out_size) {
    const float* recon_x = (const float*)d_in[0];
    const float* x       = (const float*)d_in[1];
    const float* mu      = (const float*)d_in[2];
    const float* logvar  = (const float*)d_in[3];
    const float* lt      = (const float*)d_in[4];
    const float* lr      = (const float*)d_in[5];
    const float* pmu     = (const float*)d_in[6];
    const float* plv     = (const float*)d_in[7];

    const int D = 400;
    const int B = in_sizes[2] / D;
    const int N = in_sizes[0] / B;

    fused_loss_kernel<<<B * CHUNKS, NTHR>>>(recon_x, x, lt, lr, mu, logvar,
                                            pmu, plv, (float*)d_out, B, N, D);
}